// round 2
// baseline (speedup 1.0000x reference)
#include <cuda_runtime.h>
#include <math.h>

#define N_NODES 1024
#define N_EDGES 16384
#define D_IN    128
#define ED      16
#define KTOP    8
#define NEG_INF -1000000000.0f

// ---------------- scratch (device globals) ----------------------------------
__device__ int   g_minEdge[N_NODES * N_NODES];
__device__ int   g_maxEdge[N_NODES * N_NODES];
__device__ float g_xwnode[N_NODES];
__device__ float g_xwnb[N_NODES];
__device__ float g_eval[N_EDGES];
__device__ int   g_topi[N_NODES * KTOP];
__device__ int   g_eid[N_NODES * KTOP];
__device__ float g_den1[N_NODES * D_IN];
__device__ float g_num1[N_NODES * D_IN];
__device__ float g_den2[N_NODES * 64];
__device__ float g_num2[N_NODES * 64];
__device__ float g_h1[N_NODES * 64];

// ---------------- helpers ----------------------------------------------------
__device__ __forceinline__ unsigned long long packkey(float v, int j) {
    unsigned u = __float_as_uint(v);
    u = (u & 0x80000000u) ? ~u : (u | 0x80000000u);
    return ((unsigned long long)u << 32) | (unsigned)(1023 - j);
}
__device__ __forceinline__ unsigned long long wmax64(unsigned long long k) {
#pragma unroll
    for (int o = 16; o > 0; o >>= 1) {
        unsigned long long k2 = __shfl_xor_sync(0xffffffffu, k, o);
        if (k2 > k) k = k2;
    }
    return k;
}

// ---------------- K1: init maps + zero bufs + node dots ----------------------
__global__ void init_dots(const float* __restrict__ x,
                          const float* __restrict__ mlp_w,
                          const float* __restrict__ mlp_b) {
    int b = blockIdx.x;           // 1024 blocks = node id = map row
    int t = threadIdx.x;          // 256
    int base = b * N_NODES;
#pragma unroll
    for (int q = 0; q < 4; q++) {
        g_minEdge[base + q * 256 + t] = 0x7fffffff;
        g_maxEdge[base + q * 256 + t] = -1;
    }
    if (t < 128) { g_den1[b * 128 + t] = 0.f; g_num1[b * 128 + t] = 0.f; }
    if (t < 64)  { g_den2[b * 64 + t]  = 0.f; g_num2[b * 64 + t]  = 0.f; }

    __shared__ float red[8];
    if (t < 128) {
        float xv = x[b * 128 + t];
        float p1 = xv * mlp_w[t];
        float p2 = xv * mlp_w[128 + t];
#pragma unroll
        for (int o = 16; o > 0; o >>= 1) {
            p1 += __shfl_down_sync(0xffffffffu, p1, o);
            p2 += __shfl_down_sync(0xffffffffu, p2, o);
        }
        if ((t & 31) == 0) { red[(t >> 5) * 2] = p1; red[(t >> 5) * 2 + 1] = p2; }
    }
    __syncthreads();
    if (t == 0) {
        g_xwnode[b] = red[0] + red[2] + red[4] + red[6] + mlp_b[0];
        g_xwnb[b]   = red[1] + red[3] + red[5] + red[7];
    }
}

// ---------------- K2: edge maps + edge scalar ---------------------------------
__global__ void edge_prep(const int* __restrict__ ei,
                          const float* __restrict__ edge_attr,
                          const float* __restrict__ mlp_w) {
    int e = blockIdx.x * 256 + threadIdx.x;
    int s = ei[e];
    int d = ei[N_EDGES + e];
    int idx = s * N_NODES + d;
    atomicMin(&g_minEdge[idx], e);   // first matching edge (argmax of eq)
    atomicMax(&g_maxEdge[idx], e);   // last write wins (.set)
    float acc = 0.f;
    const float4* ea = (const float4*)(edge_attr + e * ED);
#pragma unroll
    for (int q = 0; q < 4; q++) {
        float4 v = ea[q];
        acc += v.x * mlp_w[2 * D_IN + q * 4]
             + v.y * mlp_w[2 * D_IN + q * 4 + 1]
             + v.z * mlp_w[2 * D_IN + q * 4 + 2]
             + v.w * mlp_w[2 * D_IN + q * 4 + 3];
    }
    g_eval[e] = acc;
}

// ---------------- K3: sparse softmax + gumbel + top-8 -------------------------
__global__ void row_topk(const float* __restrict__ gumbel) {
    int i = blockIdx.x;
    int t = threadIdx.x;           // 256
    int lane = t & 31, w = t >> 5; // 8 warps

    __shared__ float zrow[N_NODES];
    __shared__ int   ej[256];
    __shared__ float es[256];
    __shared__ int   scnt;
    __shared__ unsigned long long wtop[64];

    if (t == 0) scnt = 0;
    __syncthreads();

    float xi = g_xwnode[i];
#pragma unroll
    for (int q = 0; q < 4; q++) {
        int j = q * 256 + t;
        zrow[j] = 0.f;
        int me = g_maxEdge[i * N_NODES + j];
        if (me >= 0) {
            int p = atomicAdd(&scnt, 1);
            ej[p] = j;
            es[p] = xi + g_xwnb[j] + g_eval[me];
        }
    }
    __syncthreads();
    int cnt = scnt;

    // softmax over the (few) finite entries; non-edges are exact 0
    if (w == 0) {
        float lm = -3.4e38f;
        for (int p = lane; p < cnt; p += 32) lm = fmaxf(lm, es[p]);
#pragma unroll
        for (int o = 16; o > 0; o >>= 1) lm = fmaxf(lm, __shfl_xor_sync(0xffffffffu, lm, o));
        float ls = 0.f;
        for (int p = lane; p < cnt; p += 32) ls += expf(es[p] - lm);
#pragma unroll
        for (int o = 16; o > 0; o >>= 1) ls += __shfl_xor_sync(0xffffffffu, ls, o);
        float inv = 1.f / ls;
        for (int p = lane; p < cnt; p += 32) zrow[ej[p]] = expf(es[p] - lm) * inv;
    }
    __syncthreads();
    float zadd = (cnt == 0) ? (1.f / 1024.f) : 0.f;  // empty row: uniform softmax

    // per-warp top-8: warp w owns j in [w*128, w*128+128)
    int jb = w * 128 + lane;
    unsigned long long k0, k1, k2, k3;
    {
        int j = jb;
        float u = gumbel[i * N_NODES + j];
        float g = -logf(-logf(u + 1e-20f) + 1e-20f);
        k0 = packkey(g + zrow[j] + zadd, j);
        j = jb + 32;
        u = gumbel[i * N_NODES + j];
        g = -logf(-logf(u + 1e-20f) + 1e-20f);
        k1 = packkey(g + zrow[j] + zadd, j);
        j = jb + 64;
        u = gumbel[i * N_NODES + j];
        g = -logf(-logf(u + 1e-20f) + 1e-20f);
        k2 = packkey(g + zrow[j] + zadd, j);
        j = jb + 96;
        u = gumbel[i * N_NODES + j];
        g = -logf(-logf(u + 1e-20f) + 1e-20f);
        k3 = packkey(g + zrow[j] + zadd, j);
    }
#pragma unroll
    for (int r = 0; r < 8; r++) {
        unsigned long long best = k0;
        if (k1 > best) best = k1;
        if (k2 > best) best = k2;
        if (k3 > best) best = k3;
        unsigned long long m = wmax64(best);
        if (k0 == m) k0 = 0; else if (k1 == m) k1 = 0;
        else if (k2 == m) k2 = 0; else if (k3 == m) k3 = 0;
        if (lane == 0) wtop[w * 8 + r] = m;
    }
    __syncthreads();

    if (w == 0) {
        unsigned long long a = wtop[lane];
        unsigned long long b = wtop[32 + lane];
        unsigned long long winkey = 0;
#pragma unroll
        for (int r = 0; r < 8; r++) {
            unsigned long long best = (a > b) ? a : b;
            unsigned long long m = wmax64(best);
            if (a == m) a = 0; else if (b == m) b = 0;
            if (lane == r) winkey = m;
        }
        if (lane < 8) {
            int j = 1023 - (int)(winkey & 0xFFFFFFFFull);
            g_topi[i * KTOP + lane] = j;
            int me = g_minEdge[i * N_NODES + j];
            g_eid[i * KTOP + lane] = (me < N_EDGES) ? me : 0;
        }
    }
}

// ---------------- K4/K6: per-src edge messages + aggregation ------------------
// No max-subtraction: m in [1e-7, ~6] so exp(m) is safe; ratio num/den identical.
template <int DIN, bool CONV2>
__global__ void conv_edge(const float* __restrict__ x,
                          const float* __restrict__ edge_attr,
                          const float* __restrict__ We,
                          const float* __restrict__ be) {
    int src = blockIdx.x;
    int f = threadIdx.x;  // DIN threads
    __shared__ float a[KTOP][ED];
    __shared__ int sdst[KTOP];
    __shared__ int seid[KTOP];
    if (f < KTOP) { sdst[f] = g_topi[src * KTOP + f]; seid[f] = g_eid[src * KTOP + f]; }
    __syncthreads();
    for (int idx = f; idx < KTOP * ED; idx += DIN) {
        int k = idx >> 4, c = idx & 15;
        a[k][c] = edge_attr[seid[k] * ED + c];
    }
    __syncthreads();

    float xv = CONV2 ? g_h1[src * DIN + f] : x[src * DIN + f];
    float beh = be[f];
    float wr[ED];
#pragma unroll
    for (int c = 0; c < ED; c++) wr[c] = We[c * DIN + f];

    float* den = CONV2 ? g_den2 : g_den1;
    float* num = CONV2 ? g_num2 : g_num1;
#pragma unroll
    for (int k = 0; k < KTOP; k++) {
        float ep = beh;
#pragma unroll
        for (int c = 0; c < ED; c++) ep += a[k][c] * wr[c];
        float m = fmaxf(xv + ep, 0.f) + 1e-7f;
        float wgt = __expf(m);
        int dst = sdst[k];
        atomicAdd(&den[dst * DIN + f], wgt);
        atomicAdd(&num[dst * DIN + f], wgt * m);
    }
}

// ---------------- K5: conv1 node MLP (16 nodes / block) -----------------------
__global__ void conv1_node(const float* __restrict__ x,
                           const float* __restrict__ W1, const float* __restrict__ b1,
                           const float* __restrict__ W2, const float* __restrict__ b2) {
    __shared__ float s0[16][128];
    __shared__ float h1s[16][256];
    int t = threadIdx.x;           // 256
    int nb = blockIdx.x * 16;
    for (int idx = t; idx < 16 * 128; idx += 256) {
        int n = idx >> 7, f = idx & 127;
        float d = g_den1[(nb + n) * 128 + f];
        float a = (d > 0.f) ? g_num1[(nb + n) * 128 + f] / d : 0.f;
        s0[n][f] = a + x[(nb + n) * 128 + f];
    }
    __syncthreads();
    float acc[16];
    float bb = b1[t];
#pragma unroll
    for (int n = 0; n < 16; n++) acc[n] = bb;
    for (int c = 0; c < 128; c++) {
        float wv = W1[c * 256 + t];
#pragma unroll
        for (int n = 0; n < 16; n++) acc[n] += s0[n][c] * wv;
    }
#pragma unroll
    for (int n = 0; n < 16; n++) h1s[n][t] = fmaxf(acc[n], 0.f);
    __syncthreads();
    int n4 = t >> 6, o = t & 63;
    float acc2[4];
    float bb2 = b2[o];
#pragma unroll
    for (int g = 0; g < 4; g++) acc2[g] = bb2;
    for (int c = 0; c < 256; c++) {
        float wv = W2[c * 64 + o];
#pragma unroll
        for (int g = 0; g < 4; g++) acc2[g] += h1s[n4 + g * 4][c] * wv;
    }
#pragma unroll
    for (int g = 0; g < 4; g++)
        g_h1[(nb + n4 + g * 4) * 64 + o] = fmaxf(acc2[g], 0.f);  // post-conv relu
}

// ---------------- K7: conv2 node MLP + final FC + mask ------------------------
__global__ void conv2_node_fc(const float* __restrict__ W1, const float* __restrict__ b1,
                              const float* __restrict__ W2, const float* __restrict__ b2,
                              const float* __restrict__ fcw, const float* __restrict__ fcb,
                              const int* __restrict__ mask, float* __restrict__ out) {
    __shared__ float s0[16][64];
    __shared__ float h1s[16][128];
    __shared__ float h2s[16][64];
    int t = threadIdx.x;           // 128
    int nb = blockIdx.x * 16;
    for (int idx = t; idx < 16 * 64; idx += 128) {
        int n = idx >> 6, f = idx & 63;
        float d = g_den2[(nb + n) * 64 + f];
        float a = (d > 0.f) ? g_num2[(nb + n) * 64 + f] / d : 0.f;
        s0[n][f] = a + g_h1[(nb + n) * 64 + f];
    }
    __syncthreads();
    float acc[16];
    float bb = b1[t];
#pragma unroll
    for (int n = 0; n < 16; n++) acc[n] = bb;
    for (int c = 0; c < 64; c++) {
        float wv = W1[c * 128 + t];
#pragma unroll
        for (int n = 0; n < 16; n++) acc[n] += s0[n][c] * wv;
    }
#pragma unroll
    for (int n = 0; n < 16; n++) h1s[n][t] = fmaxf(acc[n], 0.f);
    __syncthreads();
    int n2 = t >> 6, o = t & 63;
    float acc2[8];
    float bb2 = b2[o];
#pragma unroll
    for (int g = 0; g < 8; g++) acc2[g] = bb2;
    for (int c = 0; c < 128; c++) {
        float wv = W2[c * 64 + o];
#pragma unroll
        for (int g = 0; g < 8; g++) acc2[g] += h1s[n2 + g * 2][c] * wv;
    }
#pragma unroll
    for (int g = 0; g < 8; g++) h2s[n2 + g * 2][o] = fmaxf(acc2[g], 0.f);  // post-conv relu
    __syncthreads();
    for (int idx = t; idx < 16 * 40; idx += 128) {
        int n = idx / 40, o2 = idx % 40;
        float a2 = fcb[o2];
#pragma unroll 16
        for (int c = 0; c < 64; c++) a2 += h2s[n][c] * fcw[c * 40 + o2];
        out[(nb + n) * 40 + o2] = (mask[nb + n] != 0) ? a2 : 0.f;
    }
}

// ---------------- launch ------------------------------------------------------
extern "C" void kernel_launch(void* const* d_in, const int* in_sizes, int n_in,
                              void* d_out, int out_size) {
    const float* x         = (const float*)d_in[0];
    const float* edge_attr = (const float*)d_in[1];
    const float* gumbel    = (const float*)d_in[2];
    const float* mlp_w     = (const float*)d_in[3];
    const float* mlp_b     = (const float*)d_in[4];
    const float* c1_we = (const float*)d_in[5];
    const float* c1_be = (const float*)d_in[6];
    const float* c1_w1 = (const float*)d_in[7];
    const float* c1_b1 = (const float*)d_in[8];
    const float* c1_w2 = (const float*)d_in[9];
    const float* c1_b2 = (const float*)d_in[10];
    const float* c2_we = (const float*)d_in[11];
    const float* c2_be = (const float*)d_in[12];
    const float* c2_w1 = (const float*)d_in[13];
    const float* c2_b1 = (const float*)d_in[14];
    const float* c2_w2 = (const float*)d_in[15];
    const float* c2_b2 = (const float*)d_in[16];
    const float* fc_w  = (const float*)d_in[17];
    const float* fc_b  = (const float*)d_in[18];
    const int* edge_index = (const int*)d_in[20];
    const int* node_mask  = (const int*)d_in[21];
    float* out = (float*)d_out;

    init_dots<<<N_NODES, 256>>>(x, mlp_w, mlp_b);
    edge_prep<<<N_EDGES / 256, 256>>>(edge_index, edge_attr, mlp_w);
    row_topk<<<N_NODES, 256>>>(gumbel);

    conv_edge<D_IN, false><<<N_NODES, D_IN>>>(x, edge_attr, c1_we, c1_be);
    conv1_node<<<N_NODES / 16, 256>>>(x, c1_w1, c1_b1, c1_w2, c1_b2);

    conv_edge<64, true><<<N_NODES, 64>>>(nullptr, edge_attr, c2_we, c2_be);
    conv2_node_fc<<<N_NODES / 16, 128>>>(c2_w1, c2_b1, c2_w2, c2_b2,
                                         fc_w, fc_b, node_mask, out);
}

// round 3
// speedup vs baseline: 1.4569x; 1.4569x over previous
#include <cuda_runtime.h>
#include <math.h>

#define N_NODES 1024
#define N_EDGES 16384
#define D_IN    128
#define ED      16
#define KTOP    8
#define NBLK    296
#define NT      256

// ---------------- scratch (device globals) ----------------------------------
__device__ int   g_minEdge[N_NODES * N_NODES];
__device__ int   g_maxEdge[N_NODES * N_NODES];
__device__ float g_xwnode[N_NODES];
__device__ float g_xwnb[N_NODES];
__device__ float g_eval[N_EDGES];
__device__ int   g_topi[N_NODES * KTOP];
__device__ int   g_eid[N_NODES * KTOP];
__device__ float g_den1[N_NODES * D_IN];
__device__ float g_num1[N_NODES * D_IN];
__device__ float g_den2[N_NODES * 64];
__device__ float g_num2[N_NODES * 64];
__device__ float g_h1[N_NODES * 64];

__device__ unsigned g_count = 0;
__device__ unsigned g_gen = 0;

// ---------------- helpers ----------------------------------------------------
__device__ __forceinline__ void grid_sync(unsigned target) {
    __syncthreads();
    if (threadIdx.x == 0) {
        __threadfence();
        unsigned arrived = atomicAdd(&g_count, 1u);
        if (arrived == NBLK - 1) {
            g_count = 0;
            __threadfence();
            atomicAdd(&g_gen, 1u);
        } else {
            while (*((volatile unsigned*)&g_gen) < target) __nanosleep(64);
        }
        __threadfence();
    }
    __syncthreads();
}

__device__ __forceinline__ unsigned long long packkey(float v, int j) {
    unsigned u = __float_as_uint(v);
    u = (u & 0x80000000u) ? ~u : (u | 0x80000000u);
    return ((unsigned long long)u << 32) | (unsigned)(1023 - j);
}
__device__ __forceinline__ unsigned long long wmax64(unsigned long long k) {
#pragma unroll
    for (int o = 16; o > 0; o >>= 1) {
        unsigned long long k2 = __shfl_xor_sync(0xffffffffu, k, o);
        if (k2 > k) k = k2;
    }
    return k;
}

// ---------------- shared memory union ----------------------------------------
union SMem {
    struct {
        float zrow[N_NODES];
        int   ej[256];
        float es[256];
        unsigned long long wtop[64];
        int   scnt;
    } tk;
    struct { float s0[8][128]; float h1s[8][256]; } c1;
    struct { float s0[8][64]; float h1s[8][128]; float h2s[8][64]; } c2;
    struct { float a[2][8][16]; int sdst[2][8]; int seid[2][8]; } e1;
    struct { float a[4][8][16]; int sdst[4][8]; int seid[4][8]; } e2;
};

// ---------------- the one kernel ----------------------------------------------
__global__ void __launch_bounds__(NT, 2)
gumbel_gcn_all(const float* __restrict__ x,
               const float* __restrict__ edge_attr,
               const float* __restrict__ gumbel,
               const float* __restrict__ mlp_w,
               const float* __restrict__ mlp_b,
               const float* __restrict__ c1_we, const float* __restrict__ c1_be,
               const float* __restrict__ c1_w1, const float* __restrict__ c1_b1,
               const float* __restrict__ c1_w2, const float* __restrict__ c1_b2,
               const float* __restrict__ c2_we, const float* __restrict__ c2_be,
               const float* __restrict__ c2_w1, const float* __restrict__ c2_b1,
               const float* __restrict__ c2_w2, const float* __restrict__ c2_b2,
               const float* __restrict__ fcw, const float* __restrict__ fcb,
               const int* __restrict__ ei, const int* __restrict__ mask,
               float* __restrict__ out) {
    __shared__ SMem sm;
    const int tid = threadIdx.x;
    const int bid = blockIdx.x;
    const int gtid = bid * NT + tid;
    const int lane = tid & 31;
    const int w = tid >> 5;

    unsigned base = 0;
    if (tid == 0) base = *((volatile unsigned*)&g_gen);

    // ================= P1: init maps + zero bufs + node dots + edge eval ======
    {
        const int4 mn = make_int4(0x7fffffff, 0x7fffffff, 0x7fffffff, 0x7fffffff);
        const int4 mx = make_int4(-1, -1, -1, -1);
        const int tot4 = (N_NODES * N_NODES) / 4;
        for (int idx = gtid; idx < tot4; idx += NBLK * NT) {
            __stcg(((int4*)g_minEdge) + idx, mn);
            __stcg(((int4*)g_maxEdge) + idx, mx);
        }
        const float4 z4 = make_float4(0.f, 0.f, 0.f, 0.f);
        if (gtid < (N_NODES * D_IN) / 4) {
            __stcg(((float4*)g_den1) + gtid, z4);
            __stcg(((float4*)g_num1) + gtid, z4);
        }
        if (gtid < (N_NODES * 64) / 4) {
            __stcg(((float4*)g_den2) + gtid, z4);
            __stcg(((float4*)g_num2) + gtid, z4);
        }
        // node dots: one warp per node
        int wid = gtid >> 5;
        if (wid < N_NODES) {
            float p1 = 0.f, p2 = 0.f;
#pragma unroll
            for (int q = 0; q < 4; q++) {
                float xv = x[wid * D_IN + q * 32 + lane];
                p1 += xv * mlp_w[q * 32 + lane];
                p2 += xv * mlp_w[D_IN + q * 32 + lane];
            }
#pragma unroll
            for (int o = 16; o > 0; o >>= 1) {
                p1 += __shfl_down_sync(0xffffffffu, p1, o);
                p2 += __shfl_down_sync(0xffffffffu, p2, o);
            }
            if (lane == 0) { g_xwnode[wid] = p1 + mlp_b[0]; g_xwnb[wid] = p2; }
        }
        // edge scalar
        if (gtid < N_EDGES) {
            float acc = 0.f;
            const float4* ea = (const float4*)(edge_attr + gtid * ED);
#pragma unroll
            for (int q = 0; q < 4; q++) {
                float4 v = ea[q];
                acc += v.x * mlp_w[2 * D_IN + q * 4]
                     + v.y * mlp_w[2 * D_IN + q * 4 + 1]
                     + v.z * mlp_w[2 * D_IN + q * 4 + 2]
                     + v.w * mlp_w[2 * D_IN + q * 4 + 3];
            }
            g_eval[gtid] = acc;
        }
    }
    grid_sync(base + 1);

    // ================= P2: scatter edge ids into maps ==========================
    if (gtid < N_EDGES) {
        int s = ei[gtid];
        int d = ei[N_EDGES + gtid];
        int idx = s * N_NODES + d;
        atomicMin(&g_minEdge[idx], gtid);   // first matching edge (argmax of eq)
        atomicMax(&g_maxEdge[idx], gtid);   // last write wins (.set)
    }
    grid_sync(base + 2);

    // ================= P3: sparse softmax + gumbel + top-8 =====================
    for (int i = bid; i < N_NODES; i += NBLK) {
        if (tid == 0) sm.tk.scnt = 0;
        __syncthreads();
        float xi = g_xwnode[i];
#pragma unroll
        for (int q = 0; q < 4; q++) {
            int j = q * 256 + tid;
            sm.tk.zrow[j] = 0.f;
            int me = __ldcg(&g_maxEdge[i * N_NODES + j]);
            if (me >= 0) {
                int p = atomicAdd(&sm.tk.scnt, 1);
                sm.tk.ej[p] = j;
                sm.tk.es[p] = xi + g_xwnb[j] + g_eval[me];
            }
        }
        __syncthreads();
        int cnt = sm.tk.scnt;
        if (w == 0) {
            float lm = -3.4e38f;
            for (int p = lane; p < cnt; p += 32) lm = fmaxf(lm, sm.tk.es[p]);
#pragma unroll
            for (int o = 16; o > 0; o >>= 1) lm = fmaxf(lm, __shfl_xor_sync(0xffffffffu, lm, o));
            float ls = 0.f;
            for (int p = lane; p < cnt; p += 32) ls += expf(sm.tk.es[p] - lm);
#pragma unroll
            for (int o = 16; o > 0; o >>= 1) ls += __shfl_xor_sync(0xffffffffu, ls, o);
            float inv = 1.f / ls;
            for (int p = lane; p < cnt; p += 32)
                sm.tk.zrow[sm.tk.ej[p]] = expf(sm.tk.es[p] - lm) * inv;
        }
        __syncthreads();
        float zadd = (cnt == 0) ? (1.f / 1024.f) : 0.f;

        const float* grow = gumbel + i * N_NODES;
        int jb = w * 128 + lane;
        unsigned long long k0, k1, k2, k3;
        {
            float u, g;
            u = grow[jb];       g = -logf(-logf(u + 1e-20f) + 1e-20f);
            k0 = packkey(g + sm.tk.zrow[jb] + zadd, jb);
            u = grow[jb + 32];  g = -logf(-logf(u + 1e-20f) + 1e-20f);
            k1 = packkey(g + sm.tk.zrow[jb + 32] + zadd, jb + 32);
            u = grow[jb + 64];  g = -logf(-logf(u + 1e-20f) + 1e-20f);
            k2 = packkey(g + sm.tk.zrow[jb + 64] + zadd, jb + 64);
            u = grow[jb + 96];  g = -logf(-logf(u + 1e-20f) + 1e-20f);
            k3 = packkey(g + sm.tk.zrow[jb + 96] + zadd, jb + 96);
        }
#pragma unroll
        for (int r = 0; r < 8; r++) {
            unsigned long long best = k0;
            if (k1 > best) best = k1;
            if (k2 > best) best = k2;
            if (k3 > best) best = k3;
            unsigned long long m = wmax64(best);
            if (k0 == m) k0 = 0; else if (k1 == m) k1 = 0;
            else if (k2 == m) k2 = 0; else if (k3 == m) k3 = 0;
            if (lane == 0) sm.tk.wtop[w * 8 + r] = m;
        }
        __syncthreads();
        if (w == 0) {
            unsigned long long a = sm.tk.wtop[lane];
            unsigned long long b = sm.tk.wtop[32 + lane];
            unsigned long long winkey = 0;
#pragma unroll
            for (int r = 0; r < 8; r++) {
                unsigned long long best = (a > b) ? a : b;
                unsigned long long m = wmax64(best);
                if (a == m) a = 0; else if (b == m) b = 0;
                if (lane == r) winkey = m;
            }
            if (lane < 8) {
                int j = 1023 - (int)(winkey & 0xFFFFFFFFull);
                g_topi[i * KTOP + lane] = j;
                int me = __ldcg(&g_minEdge[i * N_NODES + j]);
                g_eid[i * KTOP + lane] = (me < N_EDGES) ? me : 0;
            }
        }
        __syncthreads();
    }
    grid_sync(base + 3);

    // ================= P4: conv1 edge messages + aggregation ===================
    {
        int sub = tid >> 7;         // 2 src nodes per block
        int f = tid & 127;
        float beh = c1_be[f];
        float wr[ED];
#pragma unroll
        for (int c = 0; c < ED; c++) wr[c] = c1_we[c * D_IN + f];
        for (int sp = bid; sp < N_NODES / 2; sp += NBLK) {
            int src = sp * 2 + sub;
            if (f < KTOP) {
                sm.e1.sdst[sub][f] = g_topi[src * KTOP + f];
                sm.e1.seid[sub][f] = g_eid[src * KTOP + f];
            }
            __syncthreads();
            {
                int k = f >> 4, c = f & 15;
                sm.e1.a[sub][k][c] = edge_attr[sm.e1.seid[sub][k] * ED + c];
            }
            __syncthreads();
            float xv = x[src * D_IN + f];
#pragma unroll
            for (int k = 0; k < KTOP; k++) {
                float ep = beh;
#pragma unroll
                for (int c = 0; c < ED; c++) ep += sm.e1.a[sub][k][c] * wr[c];
                float m = fmaxf(xv + ep, 0.f) + 1e-7f;
                float wgt = __expf(m);
                int dst = sm.e1.sdst[sub][k];
                atomicAdd(&g_den1[dst * D_IN + f], wgt);
                atomicAdd(&g_num1[dst * D_IN + f], wgt * m);
            }
            __syncthreads();
        }
    }
    grid_sync(base + 4);

    // ================= P5: conv1 node MLP (8 nodes / block) ====================
    for (int gi = bid; gi < N_NODES / 8; gi += NBLK) {
        int nb = gi * 8;
        for (int idx = tid; idx < 8 * 128; idx += NT) {
            int n = idx >> 7, ff = idx & 127;
            float d = __ldcg(&g_den1[(nb + n) * 128 + ff]);
            float nu = __ldcg(&g_num1[(nb + n) * 128 + ff]);
            sm.c1.s0[n][ff] = ((d > 0.f) ? nu / d : 0.f) + x[(nb + n) * 128 + ff];
        }
        __syncthreads();
        float acc[8];
        float bb = c1_b1[tid];
#pragma unroll
        for (int n = 0; n < 8; n++) acc[n] = bb;
        for (int c = 0; c < 128; c++) {
            float wv = c1_w1[c * 256 + tid];
#pragma unroll
            for (int n = 0; n < 8; n++) acc[n] += sm.c1.s0[n][c] * wv;
        }
#pragma unroll
        for (int n = 0; n < 8; n++) sm.c1.h1s[n][tid] = fmaxf(acc[n], 0.f);
        __syncthreads();
        int o = tid & 63, nq = (tid >> 6) * 2;
        float a0 = c1_b2[o], a1 = a0;
        for (int c = 0; c < 256; c++) {
            float wv = c1_w2[c * 64 + o];
            a0 += sm.c1.h1s[nq][c] * wv;
            a1 += sm.c1.h1s[nq + 1][c] * wv;
        }
        g_h1[(nb + nq) * 64 + o]     = fmaxf(a0, 0.f);  // post-conv relu
        g_h1[(nb + nq + 1) * 64 + o] = fmaxf(a1, 0.f);
        __syncthreads();
    }
    grid_sync(base + 5);

    // ================= P6: conv2 edge messages + aggregation ===================
    {
        int sub = tid >> 6;         // 4 src nodes per block
        int f = tid & 63;
        float beh = c2_be[f];
        float wr[ED];
#pragma unroll
        for (int c = 0; c < ED; c++) wr[c] = c2_we[c * 64 + f];
        for (int s4 = bid; s4 < N_NODES / 4; s4 += NBLK) {
            int src = s4 * 4 + sub;
            if (f < KTOP) {
                sm.e2.sdst[sub][f] = g_topi[src * KTOP + f];
                sm.e2.seid[sub][f] = g_eid[src * KTOP + f];
            }
            __syncthreads();
            for (int idx = f; idx < KTOP * ED; idx += 64) {
                int k = idx >> 4, c = idx & 15;
                sm.e2.a[sub][k][c] = edge_attr[sm.e2.seid[sub][k] * ED + c];
            }
            __syncthreads();
            float xv = g_h1[src * 64 + f];
#pragma unroll
            for (int k = 0; k < KTOP; k++) {
                float ep = beh;
#pragma unroll
                for (int c = 0; c < ED; c++) ep += sm.e2.a[sub][k][c] * wr[c];
                float m = fmaxf(xv + ep, 0.f) + 1e-7f;
                float wgt = __expf(m);
                int dst = sm.e2.sdst[sub][k];
                atomicAdd(&g_den2[dst * 64 + f], wgt);
                atomicAdd(&g_num2[dst * 64 + f], wgt * m);
            }
            __syncthreads();
        }
    }
    grid_sync(base + 6);

    // ================= P7: conv2 node MLP + final FC + mask ====================
    for (int gi = bid; gi < N_NODES / 8; gi += NBLK) {
        int nb = gi * 8;
        for (int idx = tid; idx < 8 * 64; idx += NT) {
            int n = idx >> 6, ff = idx & 63;
            float d = __ldcg(&g_den2[(nb + n) * 64 + ff]);
            float nu = __ldcg(&g_num2[(nb + n) * 64 + ff]);
            sm.c2.s0[n][ff] = ((d > 0.f) ? nu / d : 0.f) + g_h1[(nb + n) * 64 + ff];
        }
        __syncthreads();
        {
            int h = tid & 127, n4 = (tid >> 7) * 4;
            float acc[4];
            float bb = c2_b1[h];
#pragma unroll
            for (int g = 0; g < 4; g++) acc[g] = bb;
            for (int c = 0; c < 64; c++) {
                float wv = c2_w1[c * 128 + h];
#pragma unroll
                for (int g = 0; g < 4; g++) acc[g] += sm.c2.s0[n4 + g][c] * wv;
            }
#pragma unroll
            for (int g = 0; g < 4; g++) sm.c2.h1s[n4 + g][h] = fmaxf(acc[g], 0.f);
        }
        __syncthreads();
        {
            int o = tid & 63, np = (tid >> 6) * 2;
            float a0 = c2_b2[o], a1 = a0;
            for (int c = 0; c < 128; c++) {
                float wv = c2_w2[c * 64 + o];
                a0 += sm.c2.h1s[np][c] * wv;
                a1 += sm.c2.h1s[np + 1][c] * wv;
            }
            sm.c2.h2s[np][o]     = fmaxf(a0, 0.f);  // post-conv relu
            sm.c2.h2s[np + 1][o] = fmaxf(a1, 0.f);
        }
        __syncthreads();
        for (int idx = tid; idx < 8 * 40; idx += NT) {
            int n = idx / 40, o2 = idx % 40;
            float a2 = fcb[o2];
#pragma unroll 16
            for (int c = 0; c < 64; c++) a2 += sm.c2.h2s[n][c] * fcw[c * 40 + o2];
            out[(nb + n) * 40 + o2] = (mask[nb + n] != 0) ? a2 : 0.f;
        }
        __syncthreads();
    }
}

// ---------------- launch ------------------------------------------------------
extern "C" void kernel_launch(void* const* d_in, const int* in_sizes, int n_in,
                              void* d_out, int out_size) {
    gumbel_gcn_all<<<NBLK, NT>>>(
        (const float*)d_in[0],  (const float*)d_in[1],  (const float*)d_in[2],
        (const float*)d_in[3],  (const float*)d_in[4],
        (const float*)d_in[5],  (const float*)d_in[6],
        (const float*)d_in[7],  (const float*)d_in[8],
        (const float*)d_in[9],  (const float*)d_in[10],
        (const float*)d_in[11], (const float*)d_in[12],
        (const float*)d_in[13], (const float*)d_in[14],
        (const float*)d_in[15], (const float*)d_in[16],
        (const float*)d_in[17], (const float*)d_in[18],
        (const int*)d_in[20],   (const int*)d_in[21],
        (float*)d_out);
}

// round 4
// speedup vs baseline: 1.8042x; 1.2384x over previous
#include <cuda_runtime.h>
#include <math.h>

#define N_NODES 1024
#define N_EDGES 16384
#define D_IN    128
#define ED      16
#define KTOP    8
#define NBLK    296
#define NT      256
#define LCAP    64

// ---------------- scratch (device globals) ----------------------------------
__device__ int   g_rowcnt[N_NODES];
__device__ int   g_rowdst[N_NODES * LCAP];
__device__ int   g_rowe[N_NODES * LCAP];
__device__ float g_xwnode[N_NODES];
__device__ float g_xwnb[N_NODES];
__device__ float g_eval[N_EDGES];
__device__ int   g_topi[N_NODES * KTOP];
__device__ int   g_eid[N_NODES * KTOP];
__device__ float g_den1[N_NODES * D_IN];
__device__ float g_num1[N_NODES * D_IN];
__device__ float g_den2[N_NODES * 64];
__device__ float g_num2[N_NODES * 64];
__device__ float g_h1[N_NODES * 64];

__device__ unsigned g_count = 0;
__device__ unsigned g_gen = 0;

// ---------------- helpers ----------------------------------------------------
__device__ __forceinline__ void grid_sync(unsigned target) {
    __syncthreads();
    if (threadIdx.x == 0) {
        __threadfence();
        unsigned arrived = atomicAdd(&g_count, 1u);
        if (arrived == NBLK - 1) {
            g_count = 0;
            __threadfence();
            atomicAdd(&g_gen, 1u);
        } else {
            while (*((volatile unsigned*)&g_gen) < target) __nanosleep(32);
        }
        __threadfence();
    }
    __syncthreads();
}

__device__ __forceinline__ unsigned long long packkey(float v, int j) {
    unsigned u = __float_as_uint(v);
    u = (u & 0x80000000u) ? ~u : (u | 0x80000000u);
    return ((unsigned long long)u << 32) | (unsigned)(1023 - j);
}
__device__ __forceinline__ unsigned long long packu(float u, int j) {
    // u in [0,1] (positive float): bit pattern is order-preserving
    return ((unsigned long long)__float_as_uint(u) << 32) | (unsigned)(1023 - j);
}
__device__ __forceinline__ unsigned long long wmax64(unsigned long long k) {
#pragma unroll
    for (int o = 16; o > 0; o >>= 1) {
        unsigned long long k2 = __shfl_xor_sync(0xffffffffu, k, o);
        if (k2 > k) k = k2;
    }
    return k;
}

// ---------------- shared memory union ----------------------------------------
struct TK {
    int dstl[LCAP]; int el[LCAP];
    float cv[96]; int cj[96]; int ce[96];
    unsigned msk[32];
    unsigned long long wtop[32];
    float attr[KTOP][ED];
    float zadd;
    int cnt, ccnt;
    int topi8[KTOP]; int eid8[KTOP];
};
union SMem {
    TK tk[2];
    struct { float s0[4][128]; float h1s[4][256]; float hh[4][64];
             float a2[4][KTOP][ED]; int sd[4][KTOP]; int se[4][KTOP]; } c1;
    struct { float s0[4][64]; float h1s[4][128]; float h2s[4][64]; } c2;
};

// ---------------- the one kernel ----------------------------------------------
__global__ void __launch_bounds__(NT, 2)
gumbel_gcn_all(const float* __restrict__ x,
               const float* __restrict__ edge_attr,
               const float* __restrict__ gumbel,
               const float* __restrict__ mlp_w,
               const float* __restrict__ mlp_b,
               const float* __restrict__ c1_we, const float* __restrict__ c1_be,
               const float* __restrict__ c1_w1, const float* __restrict__ c1_b1,
               const float* __restrict__ c1_w2, const float* __restrict__ c1_b2,
               const float* __restrict__ c2_we, const float* __restrict__ c2_be,
               const float* __restrict__ c2_w1, const float* __restrict__ c2_b1,
               const float* __restrict__ c2_w2, const float* __restrict__ c2_b2,
               const float* __restrict__ fcw, const float* __restrict__ fcb,
               const int* __restrict__ ei, const int* __restrict__ mask,
               float* __restrict__ out) {
    __shared__ SMem sm;
    const int tid = threadIdx.x;
    const int bid = blockIdx.x;
    const int gtid = bid * NT + tid;
    const int lane = tid & 31;

    unsigned base = 0;
    if (tid == 0) base = *((volatile unsigned*)&g_gen);

    // ================= P0: zero scratch =========================================
    {
        const float4 z4 = make_float4(0.f, 0.f, 0.f, 0.f);
        if (gtid < (N_NODES * D_IN) / 4) {
            __stcg(((float4*)g_den1) + gtid, z4);
            __stcg(((float4*)g_num1) + gtid, z4);
        }
        if (gtid < (N_NODES * 64) / 4) {
            __stcg(((float4*)g_den2) + gtid, z4);
            __stcg(((float4*)g_num2) + gtid, z4);
        }
        if (gtid < N_NODES) __stcg(&g_rowcnt[gtid], 0);
    }
    grid_sync(base + 1);

    // ================= P1: node dots + edge eval + scatter lists ================
    {
        int wid = gtid >> 5;
        if (wid < N_NODES) {
            float p1 = 0.f, p2 = 0.f;
#pragma unroll
            for (int q = 0; q < 4; q++) {
                float xv = x[wid * D_IN + q * 32 + lane];
                p1 += xv * mlp_w[q * 32 + lane];
                p2 += xv * mlp_w[D_IN + q * 32 + lane];
            }
#pragma unroll
            for (int o = 16; o > 0; o >>= 1) {
                p1 += __shfl_down_sync(0xffffffffu, p1, o);
                p2 += __shfl_down_sync(0xffffffffu, p2, o);
            }
            if (lane == 0) { g_xwnode[wid] = p1 + mlp_b[0]; g_xwnb[wid] = p2; }
        }
        if (gtid < N_EDGES) {
            float acc = 0.f;
            const float4* ea = (const float4*)(edge_attr + gtid * ED);
#pragma unroll
            for (int q = 0; q < 4; q++) {
                float4 v = ea[q];
                acc += v.x * mlp_w[2 * D_IN + q * 4]
                     + v.y * mlp_w[2 * D_IN + q * 4 + 1]
                     + v.z * mlp_w[2 * D_IN + q * 4 + 2]
                     + v.w * mlp_w[2 * D_IN + q * 4 + 3];
            }
            g_eval[gtid] = acc;
            int s = ei[gtid];
            int d = ei[N_EDGES + gtid];
            int p = atomicAdd(&g_rowcnt[s], 1);
            if (p < LCAP) {
                __stcg(&g_rowdst[s * LCAP + p], d);
                __stcg(&g_rowe[s * LCAP + p], gtid);
            }
        }
    }
    grid_sync(base + 2);

    // ================= P3: topk (2 rows/block) + conv1 edge msgs ================
    {
        const int half = tid >> 7;       // 0,1
        const int htid = tid & 127;
        const int hw   = htid >> 5;      // warp within half: 0..3
        TK& tk = sm.tk[half];

#pragma unroll 1
        for (int it = 0; it < 2; it++) {
            int i = it * 2 * NBLK + bid * 2 + half;
            bool active = (i < N_NODES);

            if (htid < 32) tk.msk[htid] = 0u;
            if (htid == 0) {
                tk.ccnt = 0;
                int c = active ? __ldcg(&g_rowcnt[i]) : 0;
                tk.cnt = c < LCAP ? c : LCAP;
            }
            __syncthreads();
            int cnt = tk.cnt;

            if (htid < cnt) {
                tk.dstl[htid] = __ldcg(&g_rowdst[i * LCAP + htid]);
                tk.el[htid]   = __ldcg(&g_rowe[i * LCAP + htid]);
            }
            __syncthreads();
            if (htid < cnt) {
                int d = tk.dstl[htid], e = tk.el[htid];
                int maxe = e, mine = e;
                for (int q = 0; q < cnt; q++) {
                    if (tk.dstl[q] == d) {
                        int eq = tk.el[q];
                        maxe = max(maxe, eq); mine = min(mine, eq);
                    }
                }
                atomicOr(&tk.msk[d >> 5], 1u << (d & 31));
                if (e == maxe) {  // primary (last-written edge for this cell)
                    float s = g_xwnode[i] + g_xwnb[d] + g_eval[e];
                    int p = atomicAdd(&tk.ccnt, 1);
                    tk.cv[p] = s; tk.cj[p] = d; tk.ce[p] = mine;
                }
            }
            __syncthreads();
            int pcnt = tk.ccnt;

            // sparse softmax over primaries (1 warp per half)
            if (hw == 0) {
                float lm = -3.4e38f;
                for (int p = lane; p < pcnt; p += 32) lm = fmaxf(lm, tk.cv[p]);
#pragma unroll
                for (int o = 16; o > 0; o >>= 1) lm = fmaxf(lm, __shfl_xor_sync(0xffffffffu, lm, o));
                float ls = 0.f;
                for (int p = lane; p < pcnt; p += 32) ls += expf(tk.cv[p] - lm);
#pragma unroll
                for (int o = 16; o > 0; o >>= 1) ls += __shfl_xor_sync(0xffffffffu, ls, o);
                float inv = 1.f / ls;
                for (int p = lane; p < pcnt; p += 32)
                    tk.cv[p] = expf(tk.cv[p] - lm) * inv;
                if (lane == 0) tk.zadd = (pcnt == 0) ? (1.f / 1024.f) : 0.f;
            }
            __syncthreads();
            float zadd = tk.zadd;

            // per-warp top-8 of raw u over non-edge cells (monotone => == top-8 of g)
            unsigned long long k[8];
#pragma unroll
            for (int q = 0; q < 8; q++) k[q] = 0ull;
            if (active) {
                const float4* grow4 = (const float4*)(gumbel + (size_t)i * N_NODES);
                int jA = hw * 256 + lane * 4;
                int jB = jA + 128;
                float4 ua = grow4[jA >> 2];
                float4 ub = grow4[jB >> 2];
                unsigned wA = tk.msk[jA >> 5];
                unsigned wB = tk.msk[jB >> 5];
                if (!((wA >> ((jA & 31) + 0)) & 1u)) k[0] = packu(ua.x, jA + 0);
                if (!((wA >> ((jA & 31) + 1)) & 1u)) k[1] = packu(ua.y, jA + 1);
                if (!((wA >> ((jA & 31) + 2)) & 1u)) k[2] = packu(ua.z, jA + 2);
                if (!((wA >> ((jA & 31) + 3)) & 1u)) k[3] = packu(ua.w, jA + 3);
                if (!((wB >> ((jB & 31) + 0)) & 1u)) k[4] = packu(ub.x, jB + 0);
                if (!((wB >> ((jB & 31) + 1)) & 1u)) k[5] = packu(ub.y, jB + 1);
                if (!((wB >> ((jB & 31) + 2)) & 1u)) k[6] = packu(ub.z, jB + 2);
                if (!((wB >> ((jB & 31) + 3)) & 1u)) k[7] = packu(ub.w, jB + 3);
            }
#pragma unroll
            for (int r = 0; r < 8; r++) {
                unsigned long long best = k[0];
#pragma unroll
                for (int q = 1; q < 8; q++) if (k[q] > best) best = k[q];
                unsigned long long m = wmax64(best);
#pragma unroll
                for (int q = 0; q < 8; q++) if (k[q] == m) k[q] = 0ull;
                if (lane == 0) tk.wtop[hw * 8 + r] = m;
            }
            __syncthreads();

            // append all 32 warp winners as candidates (z = 0)
            if (htid < 32) {
                unsigned long long m = tk.wtop[htid];
                if (active && m) {
                    int p = atomicAdd(&tk.ccnt, 1);
                    tk.cv[p] = 0.f;
                    tk.cj[p] = 1023 - (int)(m & 0xFFFFFFFFull);
                    tk.ce[p] = 0;
                }
            }
            __syncthreads();
            int nc = tk.ccnt;

            // exact evaluation of <=96 candidates, top-8 with index tie-break
            if (hw == 0 && active) {
                unsigned long long kk[3];
                int ee[3]; int jj[3];
#pragma unroll
                for (int q = 0; q < 3; q++) {
                    int p = lane + q * 32;
                    kk[q] = 0ull; ee[q] = 0; jj[q] = 0;
                    if (p < nc) {
                        int j = tk.cj[p];
                        float u = gumbel[(size_t)i * N_NODES + j];
                        float g = -logf(-logf(u + 1e-20f) + 1e-20f);
                        float val = tk.cv[p] + zadd + g;
                        kk[q] = packkey(val, j);
                        ee[q] = tk.ce[p]; jj[q] = j;
                    }
                }
#pragma unroll
                for (int r = 0; r < 8; r++) {
                    unsigned long long best = kk[0];
                    if (kk[1] > best) best = kk[1];
                    if (kk[2] > best) best = kk[2];
                    unsigned long long m = wmax64(best);
#pragma unroll
                    for (int q = 0; q < 3; q++) {
                        if (kk[q] == m) {
                            tk.topi8[r] = jj[q];
                            tk.eid8[r]  = ee[q];
                            g_topi[i * KTOP + r] = jj[q];
                            g_eid[i * KTOP + r]  = ee[q];
                            kk[q] = 0ull;
                        }
                    }
                }
            }
            __syncthreads();

            // conv1 edge messages for this row (f = htid, 128 features)
            if (active) {
                int kk2 = htid >> 4, c2 = htid & 15;
                tk.attr[kk2][c2] = edge_attr[tk.eid8[kk2] * ED + c2];
            }
            __syncthreads();
            if (active) {
                int f = htid;
                float xv = x[i * D_IN + f];
                float beh = c1_be[f];
                float wr[ED];
#pragma unroll
                for (int c = 0; c < ED; c++) wr[c] = c1_we[c * D_IN + f];
#pragma unroll
                for (int kq = 0; kq < KTOP; kq++) {
                    float ep = beh;
#pragma unroll
                    for (int c = 0; c < ED; c++) ep += tk.attr[kq][c] * wr[c];
                    float m = fmaxf(xv + ep, 0.f) + 1e-7f;
                    float wgt = __expf(m);
                    int dst = tk.topi8[kq];
                    atomicAdd(&g_den1[dst * D_IN + f], wgt);
                    atomicAdd(&g_num1[dst * D_IN + f], wgt * m);
                }
            }
            __syncthreads();
        }
    }
    grid_sync(base + 3);

    // ================= P5: conv1 node MLP (4 nodes/block) + conv2 edge msgs =====
    if (bid < N_NODES / 4) {
        int nb = bid * 4;
        for (int idx = tid; idx < 4 * 128; idx += NT) {
            int n = idx >> 7, f = idx & 127;
            float d = __ldcg(&g_den1[(nb + n) * 128 + f]);
            float nu = __ldcg(&g_num1[(nb + n) * 128 + f]);
            sm.c1.s0[n][f] = ((d > 0.f) ? nu / d : 0.f) + x[(nb + n) * 128 + f];
        }
        __syncthreads();
        float acc[4];
        float bb = c1_b1[tid];
#pragma unroll
        for (int n = 0; n < 4; n++) acc[n] = bb;
        for (int c = 0; c < 128; c++) {
            float wv = c1_w1[c * 256 + tid];
#pragma unroll
            for (int n = 0; n < 4; n++) acc[n] += sm.c1.s0[n][c] * wv;
        }
#pragma unroll
        for (int n = 0; n < 4; n++) sm.c1.h1s[n][tid] = fmaxf(acc[n], 0.f);
        __syncthreads();
        {
            int o = tid & 63, n = tid >> 6;
            float a = c1_b2[o];
            for (int c = 0; c < 256; c++) a += sm.c1.h1s[n][c] * c1_w2[c * 64 + o];
            float hv = fmaxf(a, 0.f);  // post-conv relu
            g_h1[(nb + n) * 64 + o] = hv;
            sm.c1.hh[n][o] = hv;
            if (o < KTOP) {
                sm.c1.sd[n][o] = g_topi[(nb + n) * KTOP + o];
                sm.c1.se[n][o] = g_eid[(nb + n) * KTOP + o];
            }
        }
        __syncthreads();
        for (int idx = tid; idx < 4 * KTOP * ED; idx += NT) {
            int n = idx >> 7, r = idx & 127;
            int kq = r >> 4, c = r & 15;
            sm.c1.a2[n][kq][c] = edge_attr[sm.c1.se[n][kq] * ED + c];
        }
        __syncthreads();
        {
            int f = tid & 63, n = tid >> 6;
            float xv = sm.c1.hh[n][f];
            float beh = c2_be[f];
            float wr[ED];
#pragma unroll
            for (int c = 0; c < ED; c++) wr[c] = c2_we[c * 64 + f];
#pragma unroll
            for (int kq = 0; kq < KTOP; kq++) {
                float ep = beh;
#pragma unroll
                for (int c = 0; c < ED; c++) ep += sm.c1.a2[n][kq][c] * wr[c];
                float m = fmaxf(xv + ep, 0.f) + 1e-7f;
                float wgt = __expf(m);
                int dst = sm.c1.sd[n][kq];
                atomicAdd(&g_den2[dst * 64 + f], wgt);
                atomicAdd(&g_num2[dst * 64 + f], wgt * m);
            }
        }
    }
    grid_sync(base + 4);

    // ================= P7: conv2 node MLP + final FC + mask =====================
    if (bid < N_NODES / 4) {
        int nb = bid * 4;
        for (int idx = tid; idx < 4 * 64; idx += NT) {
            int n = idx >> 6, f = idx & 63;
            float d = __ldcg(&g_den2[(nb + n) * 64 + f]);
            float nu = __ldcg(&g_num2[(nb + n) * 64 + f]);
            sm.c2.s0[n][f] = ((d > 0.f) ? nu / d : 0.f) + g_h1[(nb + n) * 64 + f];
        }
        __syncthreads();
        {
            int h = tid & 127, n2 = (tid >> 7) * 2;
            float a0 = c2_b1[h], a1 = a0;
            for (int c = 0; c < 64; c++) {
                float wv = c2_w1[c * 128 + h];
                a0 += sm.c2.s0[n2][c] * wv;
                a1 += sm.c2.s0[n2 + 1][c] * wv;
            }
            sm.c2.h1s[n2][h]     = fmaxf(a0, 0.f);
            sm.c2.h1s[n2 + 1][h] = fmaxf(a1, 0.f);
        }
        __syncthreads();
        {
            int o = tid & 63, n = tid >> 6;
            float a = c2_b2[o];
            for (int c = 0; c < 128; c++) a += sm.c2.h1s[n][c] * c2_w2[c * 64 + o];
            sm.c2.h2s[n][o] = fmaxf(a, 0.f);  // post-conv relu
        }
        __syncthreads();
        for (int idx = tid; idx < 4 * 40; idx += NT) {
            int n = idx / 40, o2 = idx % 40;
            float a2 = fcb[o2];
#pragma unroll 16
            for (int c = 0; c < 64; c++) a2 += sm.c2.h2s[n][c] * fcw[c * 40 + o2];
            out[(nb + n) * 40 + o2] = (mask[nb + n] != 0) ? a2 : 0.f;
        }
    }
}

// ---------------- launch ------------------------------------------------------
extern "C" void kernel_launch(void* const* d_in, const int* in_sizes, int n_in,
                              void* d_out, int out_size) {
    gumbel_gcn_all<<<NBLK, NT>>>(
        (const float*)d_in[0],  (const float*)d_in[1],  (const float*)d_in[2],
        (const float*)d_in[3],  (const float*)d_in[4],
        (const float*)d_in[5],  (const float*)d_in[6],
        (const float*)d_in[7],  (const float*)d_in[8],
        (const float*)d_in[9],  (const float*)d_in[10],
        (const float*)d_in[11], (const float*)d_in[12],
        (const float*)d_in[13], (const float*)d_in[14],
        (const float*)d_in[15], (const float*)d_in[16],
        (const float*)d_in[17], (const float*)d_in[18],
        (const int*)d_in[20],   (const int*)d_in[21],
        (float*)d_out);
}